// round 5
// baseline (speedup 1.0000x reference)
#include <cuda_runtime.h>
#include <cuda_bf16.h>
#include <cstdint>
#include <math.h>

#define BB 4
#define SS 2048
#define DD 768
#define UU 768

// ---------------- scratch (static __device__; allocs forbidden) --------------
__device__ float g_Xr[BB * SS * DD];          // tf32-rounded x
__device__ float g_Q[BB * SS * UU];
__device__ float g_K[BB * SS * UU];
__device__ float g_V[BB * SS * UU];
__device__ float g_Vt[BB * UU * SS];
__device__ float g_Sc[(size_t)BB * SS * SS];
__device__ float g_Wqt[DD * UU];
__device__ float g_Wkt[DD * UU];
__device__ float g_Wvt[DD * UU];

// ---------------- helpers ----------------------------------------------------
__device__ __forceinline__ void cp16(uint32_t s, const void* g) {
    asm volatile("cp.async.cg.shared.global [%0], [%1], 16;\n" :: "r"(s), "l"(g) : "memory");
}
__device__ __forceinline__ void cp_commit() {
    asm volatile("cp.async.commit_group;\n" ::: "memory");
}
template <int N>
__device__ __forceinline__ void cp_wait() {
    asm volatile("cp.async.wait_group %0;\n" :: "n"(N) : "memory");
}
__device__ __forceinline__ float rnd_tf32(float f) {
    uint32_t o;
    asm("cvt.rna.tf32.f32 %0, %1;" : "=r"(o) : "f"(f));
    return __uint_as_float(o);
}
__device__ __forceinline__ void mma_tf32(float* d, const uint32_t* a, const uint32_t* b) {
    asm volatile("mma.sync.aligned.m16n8k8.row.col.f32.tf32.tf32.f32 "
                 "{%0,%1,%2,%3}, {%4,%5,%6,%7}, {%8,%9}, {%0,%1,%2,%3};"
                 : "+f"(d[0]), "+f"(d[1]), "+f"(d[2]), "+f"(d[3])
                 : "r"(a[0]), "r"(a[1]), "r"(a[2]), "r"(a[3]), "r"(b[0]), "r"(b[1]));
}

// ---------------- tf32 warp-MMA GEMM: C = alpha * A[M,K] * B[N,K]^T ----------
// CTA tile 128x256, K-chunk 16, 8 warps (2M x 4N), warp tile 64x64.
// Operands MUST already be tf32-rounded in memory (no cvt in the hot loop).
// Smem rows stride 20 floats (conflict-free fragment loads). Dynamic smem.
#define STRD 20
#define SMEM_GEMM ((128 + 256) * STRD * 4 * 2)   // 61440 B

template <bool ROUND>
__global__ __launch_bounds__(256, 1) void gemm_mma(
    const float* __restrict__ A, const float* __restrict__ B, float* __restrict__ C,
    int M, int N, int K, long sA, long sB, long sC, float alpha)
{
    extern __shared__ float sm[];
    // layout: As[2][128][STRD], Bs[2][256][STRD]
    float* Asm = sm;                         // 2*128*STRD
    float* Bsm = sm + 2 * 128 * STRD;        // 2*256*STRD

    A += (long)blockIdx.z * sA;
    B += (long)blockIdx.z * sB;
    C += (long)blockIdx.z * sC;

    const int row0 = blockIdx.y * 128;
    const int col0 = blockIdx.x * 256;
    const int tid  = threadIdx.x;
    const int wid  = tid >> 5;
    const int lane = tid & 31;
    const int g    = lane >> 2;
    const int t    = lane & 3;
    const int wm   = wid & 1;                // 0..1 -> M offset 64*wm
    const int wn   = wid >> 1;               // 0..3 -> N offset 64*wn

    const uint32_t sA0 = (uint32_t)__cvta_generic_to_shared(Asm);
    const uint32_t sB0 = (uint32_t)__cvta_generic_to_shared(Bsm);

    float acc[4][8][4];
#pragma unroll
    for (int i = 0; i < 4; i++)
#pragma unroll
        for (int j = 0; j < 8; j++)
#pragma unroll
            for (int r = 0; r < 4; r++) acc[i][j][r] = 0.f;

    const int KT = K / 16;

    // ---- tile loader: A 128x16 (512 float4), B 256x16 (1024 float4) ----
    auto load_tile = [&](int buf, int k0) {
        const uint32_t dA = sA0 + (uint32_t)(buf * 128 * STRD * 4);
        const uint32_t dB = sB0 + (uint32_t)(buf * 256 * STRD * 4);
#pragma unroll
        for (int i = 0; i < 2; i++) {
            int idx = tid + i * 256;         // 0..511
            int r   = idx >> 2;
            int c   = idx & 3;
            cp16(dA + (uint32_t)((r * STRD + c * 4) * 4),
                 A + (long)(row0 + r) * K + k0 + c * 4);
        }
#pragma unroll
        for (int i = 0; i < 4; i++) {
            int idx = tid + i * 256;         // 0..1023
            int r   = idx >> 2;
            int c   = idx & 3;
            cp16(dB + (uint32_t)((r * STRD + c * 4) * 4),
                 B + (long)(col0 + r) * K + k0 + c * 4);
        }
        cp_commit();
    };

    load_tile(0, 0);

    for (int kt = 0; kt < KT; kt++) {
        const int buf = kt & 1;
        if (kt + 1 < KT) {
            load_tile(buf ^ 1, (kt + 1) * 16);
            cp_wait<1>();
        } else {
            cp_wait<0>();
        }
        __syncthreads();

        const float* Ab = Asm + buf * 128 * STRD;
        const float* Bb = Bsm + buf * 256 * STRD;

#pragma unroll
        for (int ks = 0; ks < 2; ks++) {
            const int kb = ks * 8;
            uint32_t af[4][4], bf[8][2];
#pragma unroll
            for (int mi = 0; mi < 4; mi++) {
                const int m0 = wm * 64 + mi * 16;
                af[mi][0] = __float_as_uint(Ab[(m0 + g) * STRD + kb + t]);
                af[mi][1] = __float_as_uint(Ab[(m0 + g + 8) * STRD + kb + t]);
                af[mi][2] = __float_as_uint(Ab[(m0 + g) * STRD + kb + t + 4]);
                af[mi][3] = __float_as_uint(Ab[(m0 + g + 8) * STRD + kb + t + 4]);
            }
#pragma unroll
            for (int ni = 0; ni < 8; ni++) {
                const int n0 = wn * 64 + ni * 8;
                bf[ni][0] = __float_as_uint(Bb[(n0 + g) * STRD + kb + t]);
                bf[ni][1] = __float_as_uint(Bb[(n0 + g) * STRD + kb + t + 4]);
            }
#pragma unroll
            for (int mi = 0; mi < 4; mi++)
#pragma unroll
                for (int ni = 0; ni < 8; ni++)
                    mma_tf32(acc[mi][ni], af[mi], bf[ni]);
        }
        __syncthreads();
    }

    // ---- epilogue ----
#pragma unroll
    for (int mi = 0; mi < 4; mi++) {
        const int r0 = row0 + wm * 64 + mi * 16 + g;
#pragma unroll
        for (int ni = 0; ni < 8; ni++) {
            const int c = col0 + wn * 64 + ni * 8 + 2 * t;
            float v0 = acc[mi][ni][0] * alpha, v1 = acc[mi][ni][1] * alpha;
            float v2 = acc[mi][ni][2] * alpha, v3 = acc[mi][ni][3] * alpha;
            if (ROUND) {
                v0 = rnd_tf32(v0); v1 = rnd_tf32(v1);
                v2 = rnd_tf32(v2); v3 = rnd_tf32(v3);
            }
            *(float2*)(C + (long)r0 * N + c)       = make_float2(v0, v1);
            *(float2*)(C + (long)(r0 + 8) * N + c) = make_float2(v2, v3);
        }
    }
}

// ---------------- elementwise tf32 round-copy --------------------------------
__global__ __launch_bounds__(256) void round_copy(const float* __restrict__ in,
                                                  float* __restrict__ out, int n4)
{
    int i = blockIdx.x * 256 + threadIdx.x;
    if (i < n4) {
        float4 v = ((const float4*)in)[i];
        v.x = rnd_tf32(v.x); v.y = rnd_tf32(v.y);
        v.z = rnd_tf32(v.z); v.w = rnd_tf32(v.w);
        ((float4*)out)[i] = v;
    }
}

// ---------------- transpose (+ optional tf32 round) --------------------------
template <bool ROUND>
__global__ __launch_bounds__(256) void transpose32(
    const float* __restrict__ in, float* __restrict__ out,
    int R, int C, long sIn, long sOut)
{
    __shared__ float tbuf[32][33];
    in  += (long)blockIdx.z * sIn;
    out += (long)blockIdx.z * sOut;
    const int c0 = blockIdx.x * 32, r0 = blockIdx.y * 32;
    const int tx = threadIdx.x & 31, ty = threadIdx.x >> 5;
#pragma unroll
    for (int i = 0; i < 32; i += 8) {
        float v = in[(long)(r0 + ty + i) * C + c0 + tx];
        tbuf[ty + i][tx] = ROUND ? rnd_tf32(v) : v;
    }
    __syncthreads();
#pragma unroll
    for (int i = 0; i < 32; i += 8)
        out[(long)(c0 + ty + i) * R + r0 + tx] = tbuf[tx][ty + i];
}

// ---------------- row softmax over S=2048, writes tf32-rounded P -------------
__global__ __launch_bounds__(256) void softmax_rows(float* __restrict__ scores)
{
    float* row = scores + (long)blockIdx.x * SS;
    __shared__ float red[256];
    const int t = threadIdx.x;
    float v[8];
    float m = -INFINITY;
#pragma unroll
    for (int i = 0; i < 8; i++) { v[i] = row[t + i * 256]; m = fmaxf(m, v[i]); }
    red[t] = m; __syncthreads();
    for (int s = 128; s > 0; s >>= 1) { if (t < s) red[t] = fmaxf(red[t], red[t + s]); __syncthreads(); }
    m = red[0]; __syncthreads();
    float sum = 0.f;
#pragma unroll
    for (int i = 0; i < 8; i++) { v[i] = expf(v[i] - m); sum += v[i]; }
    red[t] = sum; __syncthreads();
    for (int s = 128; s > 0; s >>= 1) { if (t < s) red[t] += red[t + s]; __syncthreads(); }
    float inv = 1.f / red[0];
#pragma unroll
    for (int i = 0; i < 8; i++) row[t + i * 256] = rnd_tf32(v[i] * inv);
}

// ---------------------------------------------------------------------------
extern "C" void kernel_launch(void* const* d_in, const int* in_sizes, int n_in,
                              void* d_out, int out_size)
{
    (void)in_sizes; (void)n_in; (void)out_size;
    const float* x  = (const float*)d_in[0];
    const float* Wq = (const float*)d_in[1];
    const float* Wk = (const float*)d_in[2];
    const float* Wv = (const float*)d_in[3];
    float* out = (float*)d_out;

    float *Xr, *Q, *K, *V, *Vt, *Sc, *Wqt, *Wkt, *Wvt;
    cudaGetSymbolAddress((void**)&Xr,  g_Xr);
    cudaGetSymbolAddress((void**)&Q,   g_Q);
    cudaGetSymbolAddress((void**)&K,   g_K);
    cudaGetSymbolAddress((void**)&V,   g_V);
    cudaGetSymbolAddress((void**)&Vt,  g_Vt);
    cudaGetSymbolAddress((void**)&Sc,  g_Sc);
    cudaGetSymbolAddress((void**)&Wqt, g_Wqt);
    cudaGetSymbolAddress((void**)&Wkt, g_Wkt);
    cudaGetSymbolAddress((void**)&Wvt, g_Wvt);

    static bool attr_done = false;
    if (!attr_done) {
        cudaFuncSetAttribute(gemm_mma<true>,  cudaFuncAttributeMaxDynamicSharedMemorySize, SMEM_GEMM);
        cudaFuncSetAttribute(gemm_mma<false>, cudaFuncAttributeMaxDynamicSharedMemorySize, SMEM_GEMM);
        attr_done = true;
    }

    const int M = BB * SS;                       // 8192
    const float scale = 1.f / sqrtf((float)UU);

    // 0) tf32-round x; transpose+round weights [D,U] -> [U,D]
    round_copy<<<(BB * SS * DD / 4 + 255) / 256, 256>>>(x, Xr, BB * SS * DD / 4);
    dim3 tw(DD / 32, UU / 32, 1);
    transpose32<true><<<tw, 256>>>(Wq, Wqt, DD, UU, 0, 0);
    transpose32<true><<<tw, 256>>>(Wk, Wkt, DD, UU, 0, 0);
    transpose32<true><<<tw, 256>>>(Wv, Wvt, DD, UU, 0, 0);

    // 1) QKV projections (outputs rounded: they feed the next GEMMs)
    dim3 gp(UU / 256, M / 128, 1);               // (3, 64)
    gemm_mma<true><<<gp, 256, SMEM_GEMM>>>(Xr, Wqt, Q, M, UU, DD, 0, 0, 0, 1.f);
    gemm_mma<true><<<gp, 256, SMEM_GEMM>>>(Xr, Wkt, K, M, UU, DD, 0, 0, 0, 1.f);
    gemm_mma<true><<<gp, 256, SMEM_GEMM>>>(Xr, Wvt, V, M, UU, DD, 0, 0, 0, 1.f);

    // 1b) transpose V per batch: [S,U] -> [U,S] (already rounded)
    dim3 tv(UU / 32, SS / 32, BB);
    transpose32<false><<<tv, 256>>>(V, Vt, SS, UU, (long)SS * UU, (long)SS * UU);

    // 2) scores = scale * Q @ K^T (batched; NOT rounded — softmax needs fp32)
    dim3 gs(SS / 256, SS / 128, BB);             // (8, 16, 4)
    gemm_mma<false><<<gs, 256, SMEM_GEMM>>>(Q, K, Sc, SS, SS, UU,
                                            (long)SS * UU, (long)SS * UU, (long)SS * SS, scale);

    // 3) softmax rows (writes tf32-rounded P in place)
    softmax_rows<<<BB * SS, 256>>>(Sc);

    // 4) out = P @ V (batched; final output, no rounding)
    dim3 ga(UU / 256, SS / 128, BB);             // (3, 16, 4)
    gemm_mma<false><<<ga, 256, SMEM_GEMM>>>(Sc, Vt, out, SS, UU, SS,
                                            (long)SS * SS, (long)SS * UU, (long)SS * UU, 1.f);
}

// round 6
// speedup vs baseline: 1.2550x; 1.2550x over previous
#include <cuda_runtime.h>
#include <cuda_bf16.h>
#include <cstdint>
#include <math.h>

#define BB 4
#define SS 2048
#define DD 768
#define UU 768

// ---------------- scratch (static __device__; allocs forbidden) --------------
__device__ float g_Xr[BB * SS * DD];          // tf32-rounded x
__device__ float g_Q[BB * SS * UU];
__device__ float g_K[BB * SS * UU];
__device__ float g_V[BB * SS * UU];
__device__ float g_Vt[BB * UU * SS];
__device__ float g_Sc[(size_t)BB * SS * SS];
__device__ float g_Wqt[DD * UU];
__device__ float g_Wkt[DD * UU];
__device__ float g_Wvt[DD * UU];

// ---------------- helpers ----------------------------------------------------
__device__ __forceinline__ void cp16(uint32_t s, const void* g) {
    asm volatile("cp.async.cg.shared.global [%0], [%1], 16;\n" :: "r"(s), "l"(g) : "memory");
}
__device__ __forceinline__ void cp_commit() {
    asm volatile("cp.async.commit_group;\n" ::: "memory");
}
template <int N>
__device__ __forceinline__ void cp_wait() {
    asm volatile("cp.async.wait_group %0;\n" :: "n"(N) : "memory");
}
__device__ __forceinline__ float rnd_tf32(float f) {
    uint32_t o;
    asm("cvt.rna.tf32.f32 %0, %1;" : "=r"(o) : "f"(f));
    return __uint_as_float(o);
}
__device__ __forceinline__ void mma_tf32(float* d, const uint32_t* a, const uint32_t* b) {
    asm volatile("mma.sync.aligned.m16n8k8.row.col.f32.tf32.tf32.f32 "
                 "{%0,%1,%2,%3}, {%4,%5,%6,%7}, {%8,%9}, {%0,%1,%2,%3};"
                 : "+f"(d[0]), "+f"(d[1]), "+f"(d[2]), "+f"(d[3])
                 : "r"(a[0]), "r"(a[1]), "r"(a[2]), "r"(a[3]), "r"(b[0]), "r"(b[1]));
}

// ---------------- tf32 warp-MMA GEMM: C = alpha * A[M,K] * B[N,K]^T ----------
// CTA tile 128x128, K-chunk 16, 8 warps (2M x 4N), warp tile 64x32.
// Operands MUST be tf32-rounded in memory already (no cvt in hot loop).
#define STRD 20

template <bool ROUND>
__global__ __launch_bounds__(256, 2) void gemm_mma(
    const float* __restrict__ A, const float* __restrict__ B, float* __restrict__ C,
    int M, int N, int K, long sA, long sB, long sC, float alpha)
{
    __shared__ float As[2][128][STRD];
    __shared__ float Bs[2][128][STRD];

    A += (long)blockIdx.z * sA;
    B += (long)blockIdx.z * sB;
    C += (long)blockIdx.z * sC;

    const int row0 = blockIdx.y * 128;
    const int col0 = blockIdx.x * 128;
    const int tid  = threadIdx.x;
    const int wid  = tid >> 5;
    const int lane = tid & 31;
    const int g    = lane >> 2;        // 0..7
    const int t    = lane & 3;         // 0..3
    const int wm   = wid & 1;          // M half
    const int wn   = wid >> 1;         // N quarter

    const uint32_t sA0 = (uint32_t)__cvta_generic_to_shared(&As[0][0][0]);
    const uint32_t sB0 = (uint32_t)__cvta_generic_to_shared(&Bs[0][0][0]);

    float acc[4][4][4];
#pragma unroll
    for (int i = 0; i < 4; i++)
#pragma unroll
        for (int j = 0; j < 4; j++)
#pragma unroll
            for (int r = 0; r < 4; r++) acc[i][j][r] = 0.f;

    const int KT = K / 16;

    // prologue: load chunk 0 into buf 0
#pragma unroll
    for (int i = 0; i < 2; i++) {
        int idx = tid + i * 256;          // 0..511
        int r   = idx >> 2;
        int c   = idx & 3;
        cp16(sA0 + (uint32_t)((r * STRD + c * 4) * 4), A + (long)(row0 + r) * K + c * 4);
        cp16(sB0 + (uint32_t)((r * STRD + c * 4) * 4), B + (long)(col0 + r) * K + c * 4);
    }
    cp_commit();

    for (int kt = 0; kt < KT; kt++) {
        const int buf = kt & 1;
        if (kt + 1 < KT) {
            const uint32_t dA = sA0 + (uint32_t)((buf ^ 1) * 128 * STRD * 4);
            const uint32_t dB = sB0 + (uint32_t)((buf ^ 1) * 128 * STRD * 4);
            const int k0 = (kt + 1) * 16;
#pragma unroll
            for (int i = 0; i < 2; i++) {
                int idx = tid + i * 256;
                int r   = idx >> 2;
                int c   = idx & 3;
                cp16(dA + (uint32_t)((r * STRD + c * 4) * 4), A + (long)(row0 + r) * K + k0 + c * 4);
                cp16(dB + (uint32_t)((r * STRD + c * 4) * 4), B + (long)(col0 + r) * K + k0 + c * 4);
            }
            cp_commit();
            cp_wait<1>();
        } else {
            cp_wait<0>();
        }
        __syncthreads();

#pragma unroll
        for (int ks = 0; ks < 2; ks++) {
            const int kb = ks * 8;
            uint32_t af[4][4], bf[4][2];
#pragma unroll
            for (int mi = 0; mi < 4; mi++) {
                const int m0 = wm * 64 + mi * 16;
                af[mi][0] = __float_as_uint(As[buf][m0 + g][kb + t]);
                af[mi][1] = __float_as_uint(As[buf][m0 + g + 8][kb + t]);
                af[mi][2] = __float_as_uint(As[buf][m0 + g][kb + t + 4]);
                af[mi][3] = __float_as_uint(As[buf][m0 + g + 8][kb + t + 4]);
            }
#pragma unroll
            for (int ni = 0; ni < 4; ni++) {
                const int n0 = wn * 32 + ni * 8;
                bf[ni][0] = __float_as_uint(Bs[buf][n0 + g][kb + t]);
                bf[ni][1] = __float_as_uint(Bs[buf][n0 + g][kb + t + 4]);
            }
#pragma unroll
            for (int mi = 0; mi < 4; mi++)
#pragma unroll
                for (int ni = 0; ni < 4; ni++)
                    mma_tf32(acc[mi][ni], af[mi], bf[ni]);
        }
        __syncthreads();
    }

    // epilogue
#pragma unroll
    for (int mi = 0; mi < 4; mi++) {
        const int r0 = row0 + wm * 64 + mi * 16 + g;
#pragma unroll
        for (int ni = 0; ni < 4; ni++) {
            const int c = col0 + wn * 32 + ni * 8 + 2 * t;
            float v0 = acc[mi][ni][0] * alpha, v1 = acc[mi][ni][1] * alpha;
            float v2 = acc[mi][ni][2] * alpha, v3 = acc[mi][ni][3] * alpha;
            if (ROUND) {
                v0 = rnd_tf32(v0); v1 = rnd_tf32(v1);
                v2 = rnd_tf32(v2); v3 = rnd_tf32(v3);
            }
            *(float2*)(C + (long)r0 * N + c)       = make_float2(v0, v1);
            *(float2*)(C + (long)(r0 + 8) * N + c) = make_float2(v2, v3);
        }
    }
}

// ---------------- elementwise tf32 round-copy --------------------------------
__global__ __launch_bounds__(256) void round_copy(const float* __restrict__ in,
                                                  float* __restrict__ out, int n4)
{
    int i = blockIdx.x * 256 + threadIdx.x;
    if (i < n4) {
        float4 v = ((const float4*)in)[i];
        v.x = rnd_tf32(v.x); v.y = rnd_tf32(v.y);
        v.z = rnd_tf32(v.z); v.w = rnd_tf32(v.w);
        ((float4*)out)[i] = v;
    }
}

// ---------------- transpose (+ optional tf32 round) --------------------------
template <bool ROUND>
__global__ __launch_bounds__(256) void transpose32(
    const float* __restrict__ in, float* __restrict__ out,
    int R, int C, long sIn, long sOut)
{
    __shared__ float tbuf[32][33];
    in  += (long)blockIdx.z * sIn;
    out += (long)blockIdx.z * sOut;
    const int c0 = blockIdx.x * 32, r0 = blockIdx.y * 32;
    const int tx = threadIdx.x & 31, ty = threadIdx.x >> 5;
#pragma unroll
    for (int i = 0; i < 32; i += 8) {
        float v = in[(long)(r0 + ty + i) * C + c0 + tx];
        tbuf[ty + i][tx] = ROUND ? rnd_tf32(v) : v;
    }
    __syncthreads();
#pragma unroll
    for (int i = 0; i < 32; i += 8)
        out[(long)(c0 + ty + i) * R + r0 + tx] = tbuf[tx][ty + i];
}

// ---------------- row softmax over S=2048, writes tf32-rounded P -------------
__global__ __launch_bounds__(256) void softmax_rows(float* __restrict__ scores)
{
    float* row = scores + (long)blockIdx.x * SS;
    __shared__ float red[256];
    const int t = threadIdx.x;
    float v[8];
    float m = -INFINITY;
#pragma unroll
    for (int i = 0; i < 8; i++) { v[i] = row[t + i * 256]; m = fmaxf(m, v[i]); }
    red[t] = m; __syncthreads();
    for (int s = 128; s > 0; s >>= 1) { if (t < s) red[t] = fmaxf(red[t], red[t + s]); __syncthreads(); }
    m = red[0]; __syncthreads();
    float sum = 0.f;
#pragma unroll
    for (int i = 0; i < 8; i++) { v[i] = expf(v[i] - m); sum += v[i]; }
    red[t] = sum; __syncthreads();
    for (int s = 128; s > 0; s >>= 1) { if (t < s) red[t] += red[t + s]; __syncthreads(); }
    float inv = 1.f / red[0];
#pragma unroll
    for (int i = 0; i < 8; i++) row[t + i * 256] = rnd_tf32(v[i] * inv);
}

// ---------------------------------------------------------------------------
extern "C" void kernel_launch(void* const* d_in, const int* in_sizes, int n_in,
                              void* d_out, int out_size)
{
    (void)in_sizes; (void)n_in; (void)out_size;
    const float* x  = (const float*)d_in[0];
    const float* Wq = (const float*)d_in[1];
    const float* Wk = (const float*)d_in[2];
    const float* Wv = (const float*)d_in[3];
    float* out = (float*)d_out;

    float *Xr, *Q, *K, *V, *Vt, *Sc, *Wqt, *Wkt, *Wvt;
    cudaGetSymbolAddress((void**)&Xr,  g_Xr);
    cudaGetSymbolAddress((void**)&Q,   g_Q);
    cudaGetSymbolAddress((void**)&K,   g_K);
    cudaGetSymbolAddress((void**)&V,   g_V);
    cudaGetSymbolAddress((void**)&Vt,  g_Vt);
    cudaGetSymbolAddress((void**)&Sc,  g_Sc);
    cudaGetSymbolAddress((void**)&Wqt, g_Wqt);
    cudaGetSymbolAddress((void**)&Wkt, g_Wkt);
    cudaGetSymbolAddress((void**)&Wvt, g_Wvt);

    const int M = BB * SS;                       // 8192
    const float scale = 1.f / sqrtf((float)UU);

    // 0) tf32-round x; transpose+round weights [D,U] -> [U,D]
    round_copy<<<(BB * SS * DD / 4 + 255) / 256, 256>>>(x, Xr, BB * SS * DD / 4);
    dim3 tw(DD / 32, UU / 32, 1);
    transpose32<true><<<tw, 256>>>(Wq, Wqt, DD, UU, 0, 0);
    transpose32<true><<<tw, 256>>>(Wk, Wkt, DD, UU, 0, 0);
    transpose32<true><<<tw, 256>>>(Wv, Wvt, DD, UU, 0, 0);

    // 1) QKV projections (outputs rounded: they feed the next GEMMs)
    dim3 gp(UU / 128, M / 128, 1);               // (6, 64)
    gemm_mma<true><<<gp, 256>>>(Xr, Wqt, Q, M, UU, DD, 0, 0, 0, 1.f);
    gemm_mma<true><<<gp, 256>>>(Xr, Wkt, K, M, UU, DD, 0, 0, 0, 1.f);
    gemm_mma<true><<<gp, 256>>>(Xr, Wvt, V, M, UU, DD, 0, 0, 0, 1.f);

    // 1b) transpose V per batch: [S,U] -> [U,S] (already rounded)
    dim3 tv(UU / 32, SS / 32, BB);
    transpose32<false><<<tv, 256>>>(V, Vt, SS, UU, (long)SS * UU, (long)SS * UU);

    // 2) scores = scale * Q @ K^T (batched; NOT rounded — softmax wants fp32)
    dim3 gs(SS / 128, SS / 128, BB);             // (16, 16, 4)
    gemm_mma<false><<<gs, 256>>>(Q, K, Sc, SS, SS, UU,
                                 (long)SS * UU, (long)SS * UU, (long)SS * SS, scale);

    // 3) softmax rows (writes tf32-rounded P in place)
    softmax_rows<<<BB * SS, 256>>>(Sc);

    // 4) out = P @ V (batched; final output, no rounding)
    dim3 ga(UU / 128, SS / 128, BB);             // (6, 16, 4)
    gemm_mma<false><<<ga, 256>>>(Sc, Vt, out, SS, UU, SS,
                                 (long)SS * SS, (long)SS * UU, (long)SS * UU, 1.f);
}

// round 7
// speedup vs baseline: 2.2301x; 1.7769x over previous
#include <cuda_runtime.h>
#include <cuda_fp16.h>
#include <cstdint>
#include <math.h>

#define BB 4
#define SS 2048
#define DD 768
#define UU 768

// ---------------- scratch (static __device__; allocs forbidden) --------------
__device__ __half g_Xh[BB * SS * DD];
__device__ __half g_Qh[BB * SS * UU];
__device__ __half g_Kh[BB * SS * UU];
__device__ __half g_Vh[BB * SS * UU];
__device__ __half g_Vth[BB * UU * SS];
__device__ __half g_Wqt[DD * UU];
__device__ __half g_Wkt[DD * UU];
__device__ __half g_Wvt[DD * UU];
__device__ float  g_Sc[(size_t)BB * SS * SS];
__device__ __half g_P[(size_t)BB * SS * SS];

// ---------------- helpers ----------------------------------------------------
__device__ __forceinline__ void cp16(uint32_t s, const void* g) {
    asm volatile("cp.async.cg.shared.global [%0], [%1], 16;\n" :: "r"(s), "l"(g) : "memory");
}
__device__ __forceinline__ void cp_commit() {
    asm volatile("cp.async.commit_group;\n" ::: "memory");
}
template <int N>
__device__ __forceinline__ void cp_wait() {
    asm volatile("cp.async.wait_group %0;\n" :: "n"(N) : "memory");
}
__device__ __forceinline__ void mma_f16(float* d, const uint32_t* a, const uint32_t* b) {
    asm volatile("mma.sync.aligned.m16n8k16.row.col.f32.f16.f16.f32 "
                 "{%0,%1,%2,%3}, {%4,%5,%6,%7}, {%8,%9}, {%0,%1,%2,%3};"
                 : "+f"(d[0]), "+f"(d[1]), "+f"(d[2]), "+f"(d[3])
                 : "r"(a[0]), "r"(a[1]), "r"(a[2]), "r"(a[3]), "r"(b[0]), "r"(b[1]));
}

// ---------------- fp16 warp-MMA GEMM: C = alpha * A[M,K] * B[N,K]^T ----------
// A,B half in gmem. CTA tile 128x128, K-chunk 32 (halves), 8 warps (2M x 4N),
// warp tile 64x32. Smem rows stride 40 halves -> conflict-free half2 LDS.
#define STRDH 40

template <bool HALF_OUT>
__global__ __launch_bounds__(256, 2) void gemm_h(
    const __half* __restrict__ A, const __half* __restrict__ B, void* __restrict__ Cv,
    int M, int N, int K, long sA, long sB, long sC, float alpha)
{
    __shared__ __half As[2][128][STRDH];
    __shared__ __half Bs[2][128][STRDH];

    A += (long)blockIdx.z * sA;
    B += (long)blockIdx.z * sB;

    const int row0 = blockIdx.y * 128;
    const int col0 = blockIdx.x * 128;
    const int tid  = threadIdx.x;
    const int wid  = tid >> 5;
    const int lane = tid & 31;
    const int g    = lane >> 2;        // 0..7
    const int t    = lane & 3;         // 0..3
    const int wm   = wid & 1;
    const int wn   = wid >> 1;

    const uint32_t sA0 = (uint32_t)__cvta_generic_to_shared(&As[0][0][0]);
    const uint32_t sB0 = (uint32_t)__cvta_generic_to_shared(&Bs[0][0][0]);

    float acc[4][4][4];
#pragma unroll
    for (int i = 0; i < 4; i++)
#pragma unroll
        for (int j = 0; j < 4; j++)
#pragma unroll
            for (int r = 0; r < 4; r++) acc[i][j][r] = 0.f;

    const int KT = K / 32;

    // prologue: K-chunk 0 -> buf 0.  Per matrix: 128 rows x 4 chunks of 8 halves.
#pragma unroll
    for (int i = 0; i < 2; i++) {
        int idx = tid + i * 256;          // 0..511
        int r   = idx >> 2;
        int c   = idx & 3;
        cp16(sA0 + (uint32_t)((r * STRDH + c * 8) * 2), A + (long)(row0 + r) * K + c * 8);
        cp16(sB0 + (uint32_t)((r * STRDH + c * 8) * 2), B + (long)(col0 + r) * K + c * 8);
    }
    cp_commit();

    for (int kt = 0; kt < KT; kt++) {
        const int buf = kt & 1;
        if (kt + 1 < KT) {
            const uint32_t dA = sA0 + (uint32_t)((buf ^ 1) * 128 * STRDH * 2);
            const uint32_t dB = sB0 + (uint32_t)((buf ^ 1) * 128 * STRDH * 2);
            const int k0 = (kt + 1) * 32;
#pragma unroll
            for (int i = 0; i < 2; i++) {
                int idx = tid + i * 256;
                int r   = idx >> 2;
                int c   = idx & 3;
                cp16(dA + (uint32_t)((r * STRDH + c * 8) * 2), A + (long)(row0 + r) * K + k0 + c * 8);
                cp16(dB + (uint32_t)((r * STRDH + c * 8) * 2), B + (long)(col0 + r) * K + k0 + c * 8);
            }
            cp_commit();
            cp_wait<1>();
        } else {
            cp_wait<0>();
        }
        __syncthreads();

#pragma unroll
        for (int ks = 0; ks < 2; ks++) {      // two k16 steps per chunk
            const int kb = ks * 16;
            uint32_t af[4][4], bf[4][2];
#pragma unroll
            for (int mi = 0; mi < 4; mi++) {
                const int m0 = wm * 64 + mi * 16;
                af[mi][0] = *(const uint32_t*)&As[buf][m0 + g][kb + 2 * t];
                af[mi][1] = *(const uint32_t*)&As[buf][m0 + g + 8][kb + 2 * t];
                af[mi][2] = *(const uint32_t*)&As[buf][m0 + g][kb + 8 + 2 * t];
                af[mi][3] = *(const uint32_t*)&As[buf][m0 + g + 8][kb + 8 + 2 * t];
            }
#pragma unroll
            for (int ni = 0; ni < 4; ni++) {
                const int n0 = wn * 32 + ni * 8;
                bf[ni][0] = *(const uint32_t*)&Bs[buf][n0 + g][kb + 2 * t];
                bf[ni][1] = *(const uint32_t*)&Bs[buf][n0 + g][kb + 8 + 2 * t];
            }
#pragma unroll
            for (int mi = 0; mi < 4; mi++)
#pragma unroll
                for (int ni = 0; ni < 4; ni++)
                    mma_f16(acc[mi][ni], af[mi], bf[ni]);
        }
        __syncthreads();
    }

    // epilogue
#pragma unroll
    for (int mi = 0; mi < 4; mi++) {
        const int r0 = row0 + wm * 64 + mi * 16 + g;
#pragma unroll
        for (int ni = 0; ni < 4; ni++) {
            const int c = col0 + wn * 32 + ni * 8 + 2 * t;
            float v0 = acc[mi][ni][0] * alpha, v1 = acc[mi][ni][1] * alpha;
            float v2 = acc[mi][ni][2] * alpha, v3 = acc[mi][ni][3] * alpha;
            if (HALF_OUT) {
                __half* C = (__half*)Cv + (long)blockIdx.z * sC;
                *(__half2*)(C + (long)r0 * N + c)       = __floats2half2_rn(v0, v1);
                *(__half2*)(C + (long)(r0 + 8) * N + c) = __floats2half2_rn(v2, v3);
            } else {
                float* C = (float*)Cv + (long)blockIdx.z * sC;
                *(float2*)(C + (long)r0 * N + c)       = make_float2(v0, v1);
                *(float2*)(C + (long)(r0 + 8) * N + c) = make_float2(v2, v3);
            }
        }
    }
}

// ---------------- fp32 -> fp16 copy ------------------------------------------
__global__ __launch_bounds__(256) void cvt_half(const float* __restrict__ in,
                                                __half* __restrict__ out, int n4)
{
    int i = blockIdx.x * 256 + threadIdx.x;
    if (i < n4) {
        float4 v = ((const float4*)in)[i];
        __half2 h0 = __floats2half2_rn(v.x, v.y);
        __half2 h1 = __floats2half2_rn(v.z, v.w);
        ((__half2*)out)[2 * i]     = h0;
        ((__half2*)out)[2 * i + 1] = h1;
    }
}

// ---------------- transpose float->half: out[c][r] = (half)in[r][c] ----------
__global__ __launch_bounds__(256) void transpose_f2h(
    const float* __restrict__ in, __half* __restrict__ out, int R, int C)
{
    __shared__ float tbuf[32][33];
    const int c0 = blockIdx.x * 32, r0 = blockIdx.y * 32;
    const int tx = threadIdx.x & 31, ty = threadIdx.x >> 5;
#pragma unroll
    for (int i = 0; i < 32; i += 8)
        tbuf[ty + i][tx] = in[(long)(r0 + ty + i) * C + c0 + tx];
    __syncthreads();
#pragma unroll
    for (int i = 0; i < 32; i += 8)
        out[(long)(c0 + ty + i) * R + r0 + tx] = __float2half_rn(tbuf[tx][ty + i]);
}

// ---------------- transpose half->half ---------------------------------------
__global__ __launch_bounds__(256) void transpose_h(
    const __half* __restrict__ in, __half* __restrict__ out,
    int R, int C, long sIn, long sOut)
{
    __shared__ float tbuf[32][33];
    in  += (long)blockIdx.z * sIn;
    out += (long)blockIdx.z * sOut;
    const int c0 = blockIdx.x * 32, r0 = blockIdx.y * 32;
    const int tx = threadIdx.x & 31, ty = threadIdx.x >> 5;
#pragma unroll
    for (int i = 0; i < 32; i += 8)
        tbuf[ty + i][tx] = __half2float(in[(long)(r0 + ty + i) * C + c0 + tx]);
    __syncthreads();
#pragma unroll
    for (int i = 0; i < 32; i += 8)
        out[(long)(c0 + ty + i) * R + r0 + tx] = __float2half_rn(tbuf[tx][ty + i]);
}

// ---------------- row softmax over S=2048: float in, half out ----------------
__global__ __launch_bounds__(256) void softmax_rows(const float* __restrict__ scores,
                                                    __half* __restrict__ P)
{
    const float* row = scores + (long)blockIdx.x * SS;
    __half* prow = P + (long)blockIdx.x * SS;
    __shared__ float red[256];
    const int t = threadIdx.x;
    float v[8];
    float m = -INFINITY;
#pragma unroll
    for (int i = 0; i < 8; i++) { v[i] = row[t + i * 256]; m = fmaxf(m, v[i]); }
    red[t] = m; __syncthreads();
    for (int s = 128; s > 0; s >>= 1) { if (t < s) red[t] = fmaxf(red[t], red[t + s]); __syncthreads(); }
    m = red[0]; __syncthreads();
    float sum = 0.f;
#pragma unroll
    for (int i = 0; i < 8; i++) { v[i] = expf(v[i] - m); sum += v[i]; }
    red[t] = sum; __syncthreads();
    for (int s = 128; s > 0; s >>= 1) { if (t < s) red[t] += red[t + s]; __syncthreads(); }
    float inv = 1.f / red[0];
#pragma unroll
    for (int i = 0; i < 8; i++) prow[t + i * 256] = __float2half_rn(v[i] * inv);
}

// ---------------------------------------------------------------------------
extern "C" void kernel_launch(void* const* d_in, const int* in_sizes, int n_in,
                              void* d_out, int out_size)
{
    (void)in_sizes; (void)n_in; (void)out_size;
    const float* x  = (const float*)d_in[0];
    const float* Wq = (const float*)d_in[1];
    const float* Wk = (const float*)d_in[2];
    const float* Wv = (const float*)d_in[3];
    float* out = (float*)d_out;

    __half *Xh, *Qh, *Kh, *Vh, *Vth, *Wqt, *Wkt, *Wvt, *P;
    float *Sc;
    cudaGetSymbolAddress((void**)&Xh,  g_Xh);
    cudaGetSymbolAddress((void**)&Qh,  g_Qh);
    cudaGetSymbolAddress((void**)&Kh,  g_Kh);
    cudaGetSymbolAddress((void**)&Vh,  g_Vh);
    cudaGetSymbolAddress((void**)&Vth, g_Vth);
    cudaGetSymbolAddress((void**)&Wqt, g_Wqt);
    cudaGetSymbolAddress((void**)&Wkt, g_Wkt);
    cudaGetSymbolAddress((void**)&Wvt, g_Wvt);
    cudaGetSymbolAddress((void**)&Sc,  g_Sc);
    cudaGetSymbolAddress((void**)&P,   g_P);

    const int M = BB * SS;                       // 8192
    const float scale = 1.f / sqrtf((float)UU);

    // 0) convert x to half; transpose+convert weights [D,U] -> [U,D] half
    cvt_half<<<(BB * SS * DD / 4 + 255) / 256, 256>>>(x, Xh, BB * SS * DD / 4);
    dim3 tw(UU / 32, DD / 32, 1);
    transpose_f2h<<<tw, 256>>>(Wq, Wqt, DD, UU);
    transpose_f2h<<<tw, 256>>>(Wk, Wkt, DD, UU);
    transpose_f2h<<<tw, 256>>>(Wv, Wvt, DD, UU);

    // 1) QKV projections -> half
    dim3 gp(UU / 128, M / 128, 1);               // (6, 64)
    gemm_h<true><<<gp, 256>>>(Xh, Wqt, Qh, M, UU, DD, 0, 0, 0, 1.f);
    gemm_h<true><<<gp, 256>>>(Xh, Wkt, Kh, M, UU, DD, 0, 0, 0, 1.f);
    gemm_h<true><<<gp, 256>>>(Xh, Wvt, Vh, M, UU, DD, 0, 0, 0, 1.f);

    // 1b) transpose V per batch: [S,U] -> [U,S]
    dim3 tv(UU / 32, SS / 32, BB);
    transpose_h<<<tv, 256>>>(Vh, Vth, SS, UU, (long)SS * UU, (long)SS * UU);

    // 2) scores = scale * Q @ K^T (batched) -> float
    dim3 gs(SS / 128, SS / 128, BB);             // (16, 16, 4)
    gemm_h<false><<<gs, 256>>>(Qh, Kh, Sc, SS, SS, UU,
                               (long)SS * UU, (long)SS * UU, (long)SS * SS, scale);

    // 3) softmax rows: float scores -> half P
    softmax_rows<<<BB * SS, 256>>>(Sc, P);

    // 4) out = P @ V (batched) -> float
    dim3 ga(UU / 128, SS / 128, BB);             // (6, 16, 4)
    gemm_h<false><<<ga, 256>>>(P, Vth, out, SS, UU, SS,
                               (long)SS * SS, (long)SS * UU, (long)SS * UU, 1.f);
}

// round 8
// speedup vs baseline: 2.3817x; 1.0680x over previous
#include <cuda_runtime.h>
#include <cuda_fp16.h>
#include <cstdint>
#include <math.h>

#define BB 4
#define SS 2048
#define DD 768
#define UU 768

// ---------------- scratch (static __device__; allocs forbidden) --------------
__device__ __half g_Xh[BB * SS * DD];
__device__ __half g_Qh[BB * SS * UU];
__device__ __half g_Kh[BB * SS * UU];
__device__ __half g_Vh[BB * SS * UU];
__device__ __half g_Vth[BB * UU * SS];
__device__ __half g_Wqt[DD * UU];
__device__ __half g_Wkt[DD * UU];
__device__ __half g_Wvt[DD * UU];
__device__ float  g_Sc[(size_t)BB * SS * SS];
__device__ __half g_P[(size_t)BB * SS * SS];

// ---------------- helpers ----------------------------------------------------
__device__ __forceinline__ void cp16(uint32_t s, const void* g) {
    asm volatile("cp.async.cg.shared.global [%0], [%1], 16;\n" :: "r"(s), "l"(g) : "memory");
}
__device__ __forceinline__ void cp_commit() {
    asm volatile("cp.async.commit_group;\n" ::: "memory");
}
template <int N>
__device__ __forceinline__ void cp_wait() {
    asm volatile("cp.async.wait_group %0;\n" :: "n"(N) : "memory");
}
__device__ __forceinline__ void mma_f16(float* d, const uint32_t* a, const uint32_t* b) {
    asm volatile("mma.sync.aligned.m16n8k16.row.col.f32.f16.f16.f32 "
                 "{%0,%1,%2,%3}, {%4,%5,%6,%7}, {%8,%9}, {%0,%1,%2,%3};"
                 : "+f"(d[0]), "+f"(d[1]), "+f"(d[2]), "+f"(d[3])
                 : "r"(a[0]), "r"(a[1]), "r"(a[2]), "r"(a[3]), "r"(b[0]), "r"(b[1]));
}
__device__ __forceinline__ void ldsm4(uint32_t& r0, uint32_t& r1, uint32_t& r2, uint32_t& r3,
                                      uint32_t addr) {
    asm volatile("ldmatrix.sync.aligned.m8n8.x4.shared.b16 {%0,%1,%2,%3}, [%4];"
                 : "=r"(r0), "=r"(r1), "=r"(r2), "=r"(r3) : "r"(addr));
}

// ---------------- fp16 warp-MMA GEMM: C = alpha * A[M,K] * B[N,K]^T ----------
// CTA tile 128x128, K-chunk 32 halves, 8 warps (2M x 4N), warp tile 64x32.
// Fragments via ldmatrix; row stride 40 halves (80B) is LDSM-conflict-free:
// 8 rows start at word-banks {0,20,8,28,16,4,24,12}, each spans 4 -> all 32.
#define STRDH 40
#define TILE_HALFS (128 * STRDH)      // halves per buffer per matrix

template <bool HALF_OUT>
__global__ __launch_bounds__(256, 2) void gemm_h(
    const __half* __restrict__ A, const __half* __restrict__ B, void* __restrict__ Cv,
    int M, int N, int K, long sA, long sB, long sC, float alpha)
{
    __shared__ __half As[2][128][STRDH];
    __shared__ __half Bs[2][128][STRDH];

    A += (long)blockIdx.z * sA;
    B += (long)blockIdx.z * sB;

    const int row0 = blockIdx.y * 128;
    const int col0 = blockIdx.x * 128;
    const int tid  = threadIdx.x;
    const int wid  = tid >> 5;
    const int lane = tid & 31;
    const int g    = lane >> 2;
    const int t    = lane & 3;
    const int wm   = wid & 1;
    const int wn   = wid >> 1;

    const uint32_t sA0 = (uint32_t)__cvta_generic_to_shared(&As[0][0][0]);
    const uint32_t sB0 = (uint32_t)__cvta_generic_to_shared(&Bs[0][0][0]);

    // ldmatrix per-lane source offsets (in halves), relative to buffer base.
    // A x4 (one m16k16 tile): lanes 0-15 -> row (lane&15), k+0 / lanes 16-31 -> row (lane&15), k+8
    const int aRow = wm * 64 + (lane & 15);
    const int aK8  = (lane >> 4) * 8;
    // B x4 (two n8k16 tiles): mi2 = lane>>3; row = (mi2>>1)*8 + (lane&7); k + (mi2&1)*8
    const int bRow = wn * 32 + ((lane >> 4) << 3) + (lane & 7);
    const int bK8  = ((lane >> 3) & 1) * 8;

    float acc[4][4][4];
#pragma unroll
    for (int i = 0; i < 4; i++)
#pragma unroll
        for (int j = 0; j < 4; j++)
#pragma unroll
            for (int r = 0; r < 4; r++) acc[i][j][r] = 0.f;

    const int KT = K / 32;

    // prologue: K-chunk 0 -> buf 0 (128 rows x 4 chunks of 8 halves, per matrix)
#pragma unroll
    for (int i = 0; i < 2; i++) {
        int idx = tid + i * 256;
        int r   = idx >> 2;
        int c   = idx & 3;
        cp16(sA0 + (uint32_t)((r * STRDH + c * 8) * 2), A + (long)(row0 + r) * K + c * 8);
        cp16(sB0 + (uint32_t)((r * STRDH + c * 8) * 2), B + (long)(col0 + r) * K + c * 8);
    }
    cp_commit();

    for (int kt = 0; kt < KT; kt++) {
        const int buf = kt & 1;
        if (kt + 1 < KT) {
            const uint32_t dA = sA0 + (uint32_t)((buf ^ 1) * TILE_HALFS * 2);
            const uint32_t dB = sB0 + (uint32_t)((buf ^ 1) * TILE_HALFS * 2);
            const int k0 = (kt + 1) * 32;
#pragma unroll
            for (int i = 0; i < 2; i++) {
                int idx = tid + i * 256;
                int r   = idx >> 2;
                int c   = idx & 3;
                cp16(dA + (uint32_t)((r * STRDH + c * 8) * 2), A + (long)(row0 + r) * K + k0 + c * 8);
                cp16(dB + (uint32_t)((r * STRDH + c * 8) * 2), B + (long)(col0 + r) * K + k0 + c * 8);
            }
            cp_commit();
            cp_wait<1>();
        } else {
            cp_wait<0>();
        }
        __syncthreads();

        const uint32_t abase = sA0 + (uint32_t)(buf * TILE_HALFS * 2);
        const uint32_t bbase = sB0 + (uint32_t)(buf * TILE_HALFS * 2);

#pragma unroll
        for (int ks = 0; ks < 2; ks++) {          // two k16 steps per chunk
            const int kb = ks * 16;
            uint32_t af[4][4], bf[4][2];
#pragma unroll
            for (int mi = 0; mi < 4; mi++) {
                uint32_t addr = abase + (uint32_t)(((aRow + mi * 16) * STRDH + kb + aK8) * 2);
                ldsm4(af[mi][0], af[mi][1], af[mi][2], af[mi][3], addr);
            }
#pragma unroll
            for (int j = 0; j < 2; j++) {         // two n-tile pairs
                uint32_t addr = bbase + (uint32_t)(((bRow + j * 16) * STRDH + kb + bK8) * 2);
                ldsm4(bf[2 * j][0], bf[2 * j][1], bf[2 * j + 1][0], bf[2 * j + 1][1], addr);
            }
#pragma unroll
            for (int mi = 0; mi < 4; mi++)
#pragma unroll
                for (int ni = 0; ni < 4; ni++)
                    mma_f16(acc[mi][ni], af[mi], bf[ni]);
        }
        __syncthreads();
    }

    // epilogue
#pragma unroll
    for (int mi = 0; mi < 4; mi++) {
        const int r0 = row0 + wm * 64 + mi * 16 + g;
#pragma unroll
        for (int ni = 0; ni < 4; ni++) {
            const int c = col0 + wn * 32 + ni * 8 + 2 * t;
            float v0 = acc[mi][ni][0] * alpha, v1 = acc[mi][ni][1] * alpha;
            float v2 = acc[mi][ni][2] * alpha, v3 = acc[mi][ni][3] * alpha;
            if (HALF_OUT) {
                __half* C = (__half*)Cv + (long)blockIdx.z * sC;
                *(__half2*)(C + (long)r0 * N + c)       = __floats2half2_rn(v0, v1);
                *(__half2*)(C + (long)(r0 + 8) * N + c) = __floats2half2_rn(v2, v3);
            } else {
                float* C = (float*)Cv + (long)blockIdx.z * sC;
                *(float2*)(C + (long)r0 * N + c)       = make_float2(v0, v1);
                *(float2*)(C + (long)(r0 + 8) * N + c) = make_float2(v2, v3);
            }
        }
    }
}

// ---------------- fp32 -> fp16 copy ------------------------------------------
__global__ __launch_bounds__(256) void cvt_half(const float* __restrict__ in,
                                                __half* __restrict__ out, int n4)
{
    int i = blockIdx.x * 256 + threadIdx.x;
    if (i < n4) {
        float4 v = ((const float4*)in)[i];
        ((__half2*)out)[2 * i]     = __floats2half2_rn(v.x, v.y);
        ((__half2*)out)[2 * i + 1] = __floats2half2_rn(v.z, v.w);
    }
}

// ---------------- transpose float->half --------------------------------------
__global__ __launch_bounds__(256) void transpose_f2h(
    const float* __restrict__ in, __half* __restrict__ out, int R, int C)
{
    __shared__ float tbuf[32][33];
    const int c0 = blockIdx.x * 32, r0 = blockIdx.y * 32;
    const int tx = threadIdx.x & 31, ty = threadIdx.x >> 5;
#pragma unroll
    for (int i = 0; i < 32; i += 8)
        tbuf[ty + i][tx] = in[(long)(r0 + ty + i) * C + c0 + tx];
    __syncthreads();
#pragma unroll
    for (int i = 0; i < 32; i += 8)
        out[(long)(c0 + ty + i) * R + r0 + tx] = __float2half_rn(tbuf[tx][ty + i]);
}

// ---------------- transpose half->half ---------------------------------------
__global__ __launch_bounds__(256) void transpose_h(
    const __half* __restrict__ in, __half* __restrict__ out,
    int R, int C, long sIn, long sOut)
{
    __shared__ float tbuf[32][33];
    in  += (long)blockIdx.z * sIn;
    out += (long)blockIdx.z * sOut;
    const int c0 = blockIdx.x * 32, r0 = blockIdx.y * 32;
    const int tx = threadIdx.x & 31, ty = threadIdx.x >> 5;
#pragma unroll
    for (int i = 0; i < 32; i += 8)
        tbuf[ty + i][tx] = __half2float(in[(long)(r0 + ty + i) * C + c0 + tx]);
    __syncthreads();
#pragma unroll
    for (int i = 0; i < 32; i += 8)
        out[(long)(c0 + ty + i) * R + r0 + tx] = __float2half_rn(tbuf[tx][ty + i]);
}

// ---------------- row softmax over S=2048: float in, half out ----------------
__global__ __launch_bounds__(256) void softmax_rows(const float* __restrict__ scores,
                                                    __half* __restrict__ P)
{
    const float* row = scores + (long)blockIdx.x * SS;
    __half* prow = P + (long)blockIdx.x * SS;
    __shared__ float red[256];
    const int t = threadIdx.x;
    float v[8];
    float m = -INFINITY;
#pragma unroll
    for (int i = 0; i < 8; i++) { v[i] = row[t + i * 256]; m = fmaxf(m, v[i]); }
    red[t] = m; __syncthreads();
    for (int s = 128; s > 0; s >>= 1) { if (t < s) red[t] = fmaxf(red[t], red[t + s]); __syncthreads(); }
    m = red[0]; __syncthreads();
    float sum = 0.f;
#pragma unroll
    for (int i = 0; i < 8; i++) { v[i] = expf(v[i] - m); sum += v[i]; }
    red[t] = sum; __syncthreads();
    for (int s = 128; s > 0; s >>= 1) { if (t < s) red[t] += red[t + s]; __syncthreads(); }
    float inv = 1.f / red[0];
#pragma unroll
    for (int i = 0; i < 8; i++) prow[t + i * 256] = __float2half_rn(v[i] * inv);
}

// ---------------------------------------------------------------------------
extern "C" void kernel_launch(void* const* d_in, const int* in_sizes, int n_in,
                              void* d_out, int out_size)
{
    (void)in_sizes; (void)n_in; (void)out_size;
    const float* x  = (const float*)d_in[0];
    const float* Wq = (const float*)d_in[1];
    const float* Wk = (const float*)d_in[2];
    const float* Wv = (const float*)d_in[3];
    float* out = (float*)d_out;

    __half *Xh, *Qh, *Kh, *Vh, *Vth, *Wqt, *Wkt, *Wvt, *P;
    float *Sc;
    cudaGetSymbolAddress((void**)&Xh,  g_Xh);
    cudaGetSymbolAddress((void**)&Qh,  g_Qh);
    cudaGetSymbolAddress((void**)&Kh,  g_Kh);
    cudaGetSymbolAddress((void**)&Vh,  g_Vh);
    cudaGetSymbolAddress((void**)&Vth, g_Vth);
    cudaGetSymbolAddress((void**)&Wqt, g_Wqt);
    cudaGetSymbolAddress((void**)&Wkt, g_Wkt);
    cudaGetSymbolAddress((void**)&Wvt, g_Wvt);
    cudaGetSymbolAddress((void**)&Sc,  g_Sc);
    cudaGetSymbolAddress((void**)&P,   g_P);

    const int M = BB * SS;                       // 8192
    const float scale = 1.f / sqrtf((float)UU);

    // 0) convert x to half; transpose+convert weights [D,U] -> [U,D] half
    cvt_half<<<(BB * SS * DD / 4 + 255) / 256, 256>>>(x, Xh, BB * SS * DD / 4);
    dim3 tw(UU / 32, DD / 32, 1);
    transpose_f2h<<<tw, 256>>>(Wq, Wqt, DD, UU);
    transpose_f2h<<<tw, 256>>>(Wk, Wkt, DD, UU);
    transpose_f2h<<<tw, 256>>>(Wv, Wvt, DD, UU);

    // 1) QKV projections -> half
    dim3 gp(UU / 128, M / 128, 1);               // (6, 64)
    gemm_h<true><<<gp, 256>>>(Xh, Wqt, Qh, M, UU, DD, 0, 0, 0, 1.f);
    gemm_h<true><<<gp, 256>>>(Xh, Wkt, Kh, M, UU, DD, 0, 0, 0, 1.f);
    gemm_h<true><<<gp, 256>>>(Xh, Wvt, Vh, M, UU, DD, 0, 0, 0, 1.f);

    // 1b) transpose V per batch: [S,U] -> [U,S]
    dim3 tv(UU / 32, SS / 32, BB);
    transpose_h<<<tv, 256>>>(Vh, Vth, SS, UU, (long)SS * UU, (long)SS * UU);

    // 2) scores = scale * Q @ K^T (batched) -> float
    dim3 gs(SS / 128, SS / 128, BB);             // (16, 16, 4)
    gemm_h<false><<<gs, 256>>>(Qh, Kh, Sc, SS, SS, UU,
                               (long)SS * UU, (long)SS * UU, (long)SS * SS, scale);

    // 3) softmax rows: float scores -> half P
    softmax_rows<<<BB * SS, 256>>>(Sc, P);

    // 4) out = P @ V (batched) -> float
    dim3 ga(UU / 128, SS / 128, BB);             // (6, 16, 4)
    gemm_h<false><<<ga, 256>>>(P, Vth, out, SS, UU, SS,
                               (long)SS * SS, (long)SS * UU, (long)SS * UU, 1.f);
}